// round 16
// baseline (speedup 1.0000x reference)
#include <cuda_runtime.h>
#include <cuda_fp16.h>
#include <cstdint>
#include <cstddef>

#define NN 32
#define CC 256
#define HH 56
#define WW 56
#define HW (HH*WW)
#define OC2 80
#define NBAND 432
#define INV_SQRT2 0.7071067811865476f

__constant__ int c_di[8] = {1,-1,0,0,1,1,-1,-1};
__constant__ int c_dj[8] = {0,0,1,-1,1,-1,1,-1};

// Scratch (static device globals)
__device__ float g_weff[(size_t)CC*25*CC];        // [c][tap5x5][o]
__device__ __half g_xh [(size_t)NN*HW*CC];        // x transposed: [n][px][c] fp16
__device__ __align__(16) __half g_wAh[(size_t)400*4096];    // conv5 A fragments
__device__ __align__(16) __half g_waggh[(size_t)625*65536]; // corr A fragments fp16
__device__ __align__(16) __half g_w2h[(size_t)16*2048];     // W2 fragments [kc][mf(8)*256]
__device__ float g_b2eff[OC2];
__device__ int   g_aggcnt[625];
__device__ int   g_aggcombo[625*20];
__device__ float g_aggcoef[625*20];

// ---------------- band helpers ----------------
__device__ __forceinline__ void band_pos(int id, int& i, int& j) {
    if (id < 112)      { i = id/WW;           j = id%WW; }
    else if (id < 224) { int t = id-112; i = 54 + t/WW; j = t%WW; }
    else               { int t = id-224; i = 2 + t/4; int k = t%4; j = (k<2)?k:(52+k); }
}

__device__ __forceinline__ uint32_t smem_u32(const void* p) {
    uint32_t a;
    asm("{ .reg .u64 t; cvta.to.shared.u64 t, %1; cvt.u32.u64 %0, t; }" : "=r"(a) : "l"(p));
    return a;
}

// ---------------- fold 9-group 3x3 -> effective 5x5 ----------------
__global__ void fold_kernel(const float* __restrict__ w1) {
    int idx = blockIdx.x * blockDim.x + threadIdx.x;
    if (idx >= CC*25*CC) return;
    int o   = idx % CC;
    int tap = (idx / CC) % 25;
    int c   = idx / (CC*25);
    int du = tap/5 - 2, dv = tap%5 - 2;
    float t = 0.f;
    if (du >= -1 && du <= 1 && dv >= -1 && dv <= 1) {
        int a = du + 1, b = dv + 1;
        t += w1[(((size_t)o*2304 + c)*3 + a)*3 + b];
        #pragma unroll
        for (int g = 0; g < 8; g++) {
            float s = (g < 4) ? 1.f : INV_SQRT2;
            t += s * w1[(((size_t)o*2304 + (g+1)*CC + c)*3 + a)*3 + b];
        }
    }
    #pragma unroll
    for (int g = 0; g < 8; g++) {
        int a = du + c_di[g] + 1, b = dv + c_dj[g] + 1;
        if (a >= 0 && a < 3 && b >= 0 && b < 3) {
            float s = (g < 4) ? 1.f : INV_SQRT2;
            t -= s * w1[(((size_t)o*2304 + (g+1)*CC + c)*3 + a)*3 + b];
        }
    }
    g_weff[((size_t)c*25 + tap)*CC + o] = t;
}

// ---------------- border-correction aggregation table (parallel) ----------
__global__ void aggtab_kernel() {
    int sc = blockIdx.x;        // 0..624
    if (threadIdx.x != 0) return;
    int cls = sc / 25, slot = sc % 25;
    int ci = cls / 5, cj = cls % 5;
    int oi = slot/5 - 2, oj = slot%5 - 2;
    const int rep[5] = {0, 1, 28, 54, 55};
    int pi = rep[ci], pj = rep[cj];
    int cnt = 0;
    if (!(ci == 2 && cj == 2)) {
        for (int g = 0; g < 8; g++) {
            int di = c_di[g], dj = c_dj[g];
            for (int a = 0; a < 3; a++) {
                for (int b = 0; b < 3; b++) {
                    int qi = pi + a - 1, qj = pj + b - 1;
                    int ui = qi - di,    uj = qj - dj;
                    bool qin = ((unsigned)qi < HH) && ((unsigned)qj < WW);
                    bool uin = ((unsigned)ui < HH) && ((unsigned)uj < WW);
                    float sgn; int si, sj;
                    if (qin && !uin)      { sgn = -1.f; si = qi; sj = qj; }
                    else if (!qin && uin) { sgn =  1.f; si = ui; sj = uj; }
                    else continue;
                    if (si - pi == oi && sj - pj == oj && cnt < 20) {
                        g_aggcombo[sc*20 + cnt] = g*9 + a*3 + b;
                        g_aggcoef [sc*20 + cnt] = sgn * ((g < 4) ? 1.f : INV_SQRT2);
                        cnt++;
                    }
                }
            }
        }
    }
    g_aggcnt[sc] = cnt;
}

// ---------------- materialize aggregated weights as fp16 MMA fragments ----
__global__ void wagg_kernel(const float* __restrict__ w1) {
    int sc = blockIdx.x;
    int kc = blockIdx.y;
    int cnt = g_aggcnt[sc];
    if (cnt == 0) return;
    int tid = threadIdx.x;
    #pragma unroll 1
    for (int h16 = 0; h16 < 16; h16++) {
        int e = tid*16 + h16;
        int h    = e & 7;
        int lane = (e >> 3) & 31;
        int mf   = e >> 8;
        int apair = h >> 1, half = h & 1;
        int o = mf*16 + (lane >> 2) + (apair & 1)*8;
        int c = kc*16 + 2*(lane & 3) + (apair >> 1)*8 + half;
        float t = 0.f;
        for (int k = 0; k < cnt; k++) {
            int combo = g_aggcombo[sc*20 + k];
            float cf  = g_aggcoef [sc*20 + k];
            int g = combo / 9, tap = combo % 9;
            t += cf * w1[((size_t)o*2304 + (g+1)*CC + c)*9 + tap];
        }
        g_waggh[(size_t)sc*65536 + kc*4096 + e] = __float2half_rn(t);
    }
}

// ---------------- W2 -> fp16 fragments ----------------
__global__ void w2prep_kernel(const float* __restrict__ w2) {
    int idx = blockIdx.x * blockDim.x + threadIdx.x;
    if (idx >= 16*2048) return;
    int e  = idx & 2047;
    int kc = idx >> 11;
    int h    = e & 7;
    int lane = (e >> 3) & 31;
    int mf   = e >> 8;
    int apair = h >> 1, half = h & 1;
    int oc2 = mf*16 + (lane >> 2) + (apair & 1)*8;
    int ko  = kc*16 + 2*(lane & 3) + (apair >> 1)*8 + half;
    float v = (mf < 5) ? w2[(size_t)oc2*CC + ko] : 0.f;
    g_w2h[idx] = __float2half_rn(v);
}

// ---------------- b2eff = b2 + W2 . b1 ----------------
__global__ void b2eff_kernel(const float* __restrict__ w2, const float* __restrict__ b1,
                             const float* __restrict__ b2) {
    int oc = threadIdx.x;
    if (oc >= OC2) return;
    float t = b2[oc];
    for (int o = 0; o < CC; o++) t += w2[(size_t)oc*CC + o] * b1[o];
    g_b2eff[oc] = t;
}

// ---------------- x transpose: [n][c][px] fp32 -> [n][px][c] fp16 ----------
__global__ void xprep_kernel(const float* __restrict__ x) {
    __shared__ float t[32][33];
    int n  = blockIdx.z;
    int cb = blockIdx.y * 32;
    int pb = blockIdx.x * 32;
    int tx = threadIdx.x & 31, ty = threadIdx.x >> 5;
    #pragma unroll
    for (int r = ty; r < 32; r += 8)
        t[r][tx] = x[((size_t)n*CC + cb + r)*HW + pb + tx];
    __syncthreads();
    #pragma unroll
    for (int r = ty; r < 32; r += 8)
        g_xh[((size_t)n*HW + pb + r)*CC + cb + tx] = __float2half_rn(t[tx][r]);
}

// ---------------- weight prep: Weff -> fp16 A fragments (8m x 2mf) --------
// tile = tap*16+cc ; e = ((w*2+mf)*32 + lane)*8 + h
//   o = w*32 + mf*16 + (lane>>2) + (apair&1)*8 ; c = 2*(lane&3) + (apair>>1)*8 + half
__global__ void wprep_kernel() {
    int idx = blockIdx.x * blockDim.x + threadIdx.x;
    if (idx >= 400*4096) return;
    int e    = idx & 4095;
    int tile = idx >> 12;
    int h     = e & 7;
    int lane  = (e >> 3) & 31;
    int wmmf  = e >> 8;                  // 0..15 = w*2+mf
    int w  = wmmf >> 1, mf = wmmf & 1;
    int apair = h >> 1, half = h & 1;
    int o = w*32 + mf*16 + (lane >> 2) + (apair & 1)*8;
    int c = 2*(lane & 3) + (apair >> 1)*8 + half;
    int ccv = tile & 15;
    int tap = tile >> 4;
    float v = g_weff[(((size_t)(ccv*16 + c))*25 + tap)*CC + o];
    g_wAh[idx] = __float2half_rn(v);
}

// ---------------- shared MMA macros ----------------
#define MMA16816(cacc, a, b0, b1) \
    asm volatile("mma.sync.aligned.m16n8k16.row.col.f32.f16.f16.f32 " \
        "{%0,%1,%2,%3}, {%4,%5,%6,%7}, {%8,%9}, {%0,%1,%2,%3};" \
        : "+f"((cacc)[0]),"+f"((cacc)[1]),"+f"((cacc)[2]),"+f"((cacc)[3]) \
        : "r"((a)[0]),"r"((a)[1]),"r"((a)[2]),"r"((a)[3]), "r"(b0),"r"(b1))

#define LDSM_X2(r0, r1, addr) \
    asm volatile("ldmatrix.sync.aligned.m8n8.x2.shared.b16 {%0,%1}, [%2];" \
        : "=r"(r0), "=r"(r1) : "r"(addr))

#define LDSM_X4(r0, r1, r2, r3, addr) \
    asm volatile("ldmatrix.sync.aligned.m8n8.x4.shared.b16 {%0,%1,%2,%3}, [%4];" \
        : "=r"(r0), "=r"(r1), "=r"(r2), "=r"(r3) : "r"(addr))

#define CP_ASYNC16(dst, src, sz) \
    asm volatile("cp.async.cg.shared.global [%0], [%1], 16, %2;" \
        :: "r"(dst), "l"(src), "r"(sz))
#define CP_COMMIT() asm volatile("cp.async.commit_group;" ::: "memory")
#define CP_WAIT0()  asm volatile("cp.async.wait_group 0;" ::: "memory")

#define STAGE_BYTES 14400           // 5*60*24 halfs * 2B
#define HS_OFF      (2*STAGE_BYTES) // h-tile offset in dynamic smem
#define HS_STRIDE   264             // halfs per px row
#define CONV5_SMEM  (HS_OFF + 56*HS_STRIDE*2)

// ---------------- conv5 fused with 1x1 (1-row tiles) ----------------------
__device__ __forceinline__ void stage_cc(uint32_t shdst, const __half* __restrict__ xnp,
                                         int i0, int cc, int tid) {
    #pragma unroll
    for (int it = 0; it < 3; it++) {
        int e = tid + it*256;
        if (e < 600) {
            int chunk = e & 1, px = e >> 1;
            int col = px % 60, row = px / 60;
            int gi = i0 - 2 + row, gj = col - 2;
            bool inb = ((unsigned)gi < HH) && ((unsigned)gj < WW);
            const __half* src = inb
                ? xnp + ((size_t)gi*WW + gj)*CC + cc*16 + chunk*8
                : xnp;
            CP_ASYNC16(shdst + px*48 + chunk*16, src, inb ? 16 : 0);
        }
    }
}

__global__ void __launch_bounds__(256) conv5_mma_kernel(float* __restrict__ out) {
    extern __shared__ __align__(16) char dsm[];
    __half* SH = (__half*)dsm;
    __half* hS = (__half*)(dsm + HS_OFF);

    int tid  = threadIdx.x;
    int lane = tid & 31, w = tid >> 5;     // 8 warps, 32 o each
    int i0 = blockIdx.x;                    // single output row
    int n  = blockIdx.y;
    const __half* xnp = g_xh + (size_t)n * HW * CC;

    float acc[2][7][4];
    #pragma unroll
    for (int mf = 0; mf < 2; mf++)
        #pragma unroll
        for (int nf = 0; nf < 7; nf++)
            #pragma unroll
            for (int q = 0; q < 4; q++) acc[mf][nf][q] = 0.f;

    uint32_t sh0 = smem_u32(SH);
    int rrow = lane & 7;
    int khalf = (lane >> 3) & 1;
    uint32_t lbase[7];
    #pragma unroll
    for (int nf = 0; nf < 7; nf++)
        lbase[nf] = sh0 + ((nf*8 + rrow)*24 + khalf*8)*2;

    const __half* aBase = g_wAh + (w*2)*256 + lane*8;

    stage_cc(sh0, xnp, i0, 0, tid);
    CP_COMMIT();
    CP_WAIT0();
    __syncthreads();

    #pragma unroll 1
    for (int cc = 0; cc < 16; cc++) {
        int buf = cc & 1;
        uint32_t bo = (uint32_t)(buf * STAGE_BYTES);

        if (cc < 15) {
            stage_cc(sh0 + (buf ^ 1)*STAGE_BYTES, xnp, i0, cc + 1, tid);
            CP_COMMIT();
        }

        uint32_t ahb[2][2][4];
        {
            const __half* tH = aBase + (size_t)cc*4096;
            #pragma unroll
            for (int mf = 0; mf < 2; mf++) {
                uint4 av = *(const uint4*)(tH + mf*256);
                ahb[0][mf][0] = av.x; ahb[0][mf][1] = av.y;
                ahb[0][mf][2] = av.z; ahb[0][mf][3] = av.w;
            }
        }

        #pragma unroll
        for (int tap = 0; tap < 25; tap++) {
            int cur = tap & 1, nxt = cur ^ 1;
            if (tap < 24) {
                const __half* tH = aBase + (size_t)((tap + 1)*16 + cc)*4096;
                #pragma unroll
                for (int mf = 0; mf < 2; mf++) {
                    uint4 av = *(const uint4*)(tH + mf*256);
                    ahb[nxt][mf][0] = av.x; ahb[nxt][mf][1] = av.y;
                    ahb[nxt][mf][2] = av.z; ahb[nxt][mf][3] = av.w;
                }
            }
            int du = tap / 5, dv = tap % 5;
            uint32_t taddr = bo + (uint32_t)((du*60 + dv)*48);
            uint32_t bm[7][2];
            #pragma unroll
            for (int nf = 0; nf < 7; nf++)
                LDSM_X2(bm[nf][0], bm[nf][1], lbase[nf] + taddr);
            #pragma unroll
            for (int nf = 0; nf < 7; nf++) {
                #pragma unroll
                for (int mf = 0; mf < 2; mf++)
                    MMA16816(acc[mf][nf], ahb[cur][mf], bm[nf][0], bm[nf][1]);
            }
        }

        if (cc < 15) {
            CP_WAIT0();
            __syncthreads();
        }
    }

    // ---- spill h-tile to SMEM as fp16 [px 56][o stride 264] ----
    __syncthreads();
    {
        int r = lane >> 2, q = 2*(lane & 3);
        #pragma unroll
        for (int mf = 0; mf < 2; mf++) {
            int o0 = w*32 + mf*16 + r;
            #pragma unroll
            for (int nf = 0; nf < 7; nf++) {
                int px = nf*8 + q;
                hS[px*HS_STRIDE + o0]           = __float2half_rn(acc[mf][nf][0]);
                hS[(px+1)*HS_STRIDE + o0]       = __float2half_rn(acc[mf][nf][1]);
                hS[px*HS_STRIDE + o0 + 8]       = __float2half_rn(acc[mf][nf][2]);
                hS[(px+1)*HS_STRIDE + o0 + 8]   = __float2half_rn(acc[mf][nf][3]);
            }
        }
    }
    __syncthreads();

    // ---- GEMM2: out[80,56] = W2 . h ; warps 0..6 take px frag = w ----
    if (w < 7) {
        uint32_t hbase = smem_u32(hS);
        float acc2[5][4];
        #pragma unroll
        for (int mf = 0; mf < 5; mf++)
            #pragma unroll
            for (int q = 0; q < 4; q++) acc2[mf][q] = 0.f;

        #pragma unroll 1
        for (int kc = 0; kc < 16; kc++) {
            uint32_t addr = hbase + (uint32_t)(((w*8 + rrow)*HS_STRIDE + kc*16 + khalf*8)*2);
            uint32_t b0, b1v;
            LDSM_X2(b0, b1v, addr);
            #pragma unroll
            for (int mf = 0; mf < 5; mf++) {
                uint4 av = *(const uint4*)(g_w2h + (size_t)(kc*8 + mf)*256 + lane*8);
                uint32_t a[4] = {av.x, av.y, av.z, av.w};
                MMA16816(acc2[mf], a, b0, b1v);
            }
        }

        int r = lane >> 2, q = 2*(lane & 3);
        #pragma unroll
        for (int mf = 0; mf < 5; mf++) {
            int oc0 = mf*16 + r;
            float bb0 = g_b2eff[oc0], bb1 = g_b2eff[oc0 + 8];
            int px = w*8 + q;
            float* o0p = out + ((size_t)n*OC2 + oc0)*HW + (size_t)i0*WW + px;
            float* o1p = o0p + (size_t)8*HW;
            *(float2*)o0p = make_float2(acc2[mf][0] + bb0, acc2[mf][1] + bb0);
            *(float2*)o1p = make_float2(acc2[mf][2] + bb1, acc2[mf][3] + bb1);
        }
    }
}

// ---------------- border correction: HMMA dH then W2.dH, RMW out ----------
__global__ void __launch_bounds__(256) corr_kernel(float* __restrict__ out) {
    __shared__ __align__(16) __half xs[32*264];
    __shared__ __align__(16) __half hC[32*264];
    int tid  = threadIdx.x;
    int lane = tid & 31, w = tid >> 5;
    int pi, pj; band_pos(blockIdx.x, pi, pj);
    int ci = pi < 2 ? pi : (pi > 53 ? pi - 51 : 2);
    int cj = pj < 2 ? pj : (pj > 53 ? pj - 51 : 2);
    int cls = ci*5 + cj;

    float acc[2][4][4];
    #pragma unroll
    for (int m = 0; m < 2; m++)
        #pragma unroll
        for (int nf = 0; nf < 4; nf++)
            #pragma unroll
            for (int q = 0; q < 4; q++) acc[m][nf][q] = 0.f;

    uint32_t sh0 = smem_u32(xs);
    int nfsel = (lane >> 4) & 1;
    int khalf = (lane >> 3) & 1;
    int row   = lane & 7;

    #pragma unroll 1
    for (int slot = 0; slot < 25; slot++) {
        int sc = cls*25 + slot;
        if (g_aggcnt[sc] == 0) continue;
        int si = pi + slot/5 - 2, sj = pj + slot%5 - 2;
        const __half* xsrc = g_xh + ((size_t)si*WW + sj)*CC;

        __syncthreads();
        #pragma unroll
        for (int it = 0; it < 4; it++) {
            int e = tid + it*256;
            int nn = e >> 5, ch = e & 31;
            uint4 v = *(const uint4*)(xsrc + (size_t)nn*HW*CC + ch*8);
            *(uint4*)(xs + nn*264 + ch*8) = v;
        }
        __syncthreads();

        const __half* aT = g_waggh + (size_t)sc*65536 + (2*w)*256 + lane*8;
        #pragma unroll 1
        for (int kc = 0; kc < 16; kc++) {
            uint4 a0v = *(const uint4*)(aT + kc*4096);
            uint4 a1v = *(const uint4*)(aT + kc*4096 + 256);
            uint32_t a0[4] = {a0v.x, a0v.y, a0v.z, a0v.w};
            uint32_t a1[4] = {a1v.x, a1v.y, a1v.z, a1v.w};
            uint32_t b[4][2];
            #pragma unroll
            for (int nfp = 0; nfp < 2; nfp++) {
                int nrow = (nfp*2 + nfsel)*8 + row;
                uint32_t addr = sh0 + (uint32_t)((nrow*264 + kc*16 + khalf*8)*2);
                uint32_t r0, r1, r2, r3;
                LDSM_X4(r0, r1, r2, r3, addr);
                b[nfp*2    ][0] = r0; b[nfp*2    ][1] = r1;
                b[nfp*2 + 1][0] = r2; b[nfp*2 + 1][1] = r3;
            }
            #pragma unroll
            for (int nf = 0; nf < 4; nf++) {
                MMA16816(acc[0][nf], a0, b[nf][0], b[nf][1]);
                MMA16816(acc[1][nf], a1, b[nf][0], b[nf][1]);
            }
        }
    }

    // spill dH to SMEM [n=32 rows][o stride 264] fp16
    __syncthreads();
    {
        int r = lane >> 2, q2 = 2*(lane & 3);
        #pragma unroll
        for (int m = 0; m < 2; m++) {
            int o0 = w*32 + m*16 + r;
            #pragma unroll
            for (int nf = 0; nf < 4; nf++) {
                int n0 = nf*8 + q2;
                hC[n0*264 + o0]           = __float2half_rn(acc[m][nf][0]);
                hC[(n0+1)*264 + o0]       = __float2half_rn(acc[m][nf][1]);
                hC[n0*264 + o0 + 8]       = __float2half_rn(acc[m][nf][2]);
                hC[(n0+1)*264 + o0 + 8]   = __float2half_rn(acc[m][nf][3]);
            }
        }
    }
    __syncthreads();

    // GEMM2: dOut[80,32] = W2 . dH ; warps 0..4 take mf = w
    if (w < 5) {
        uint32_t hbase = smem_u32(hC);
        float acc2[4][4];
        #pragma unroll
        for (int nf = 0; nf < 4; nf++)
            #pragma unroll
            for (int q = 0; q < 4; q++) acc2[nf][q] = 0.f;

        #pragma unroll 1
        for (int kc = 0; kc < 16; kc++) {
            uint4 av = *(const uint4*)(g_w2h + (size_t)(kc*8 + w)*256 + lane*8);
            uint32_t a[4] = {av.x, av.y, av.z, av.w};
            #pragma unroll
            for (int nf = 0; nf < 4; nf++) {
                uint32_t addr = hbase + (uint32_t)(((nf*8 + row)*264 + kc*16 + khalf*8)*2);
                uint32_t b0, b1v;
                LDSM_X2(b0, b1v, addr);
                MMA16816(acc2[nf], a, b0, b1v);
            }
        }

        int r = lane >> 2, q2 = 2*(lane & 3);
        size_t pix = (size_t)pi*WW + pj;
        #pragma unroll
        for (int nf = 0; nf < 4; nf++) {
            int n0 = nf*8 + q2;
            int oc0 = w*16 + r;
            float* p00 = out + ((size_t)n0*OC2 + oc0)*HW + pix;
            float* p10 = out + ((size_t)(n0+1)*OC2 + oc0)*HW + pix;
            p00[0]          += acc2[nf][0];
            p10[0]          += acc2[nf][1];
            p00[(size_t)8*HW] += acc2[nf][2];
            p10[(size_t)8*HW] += acc2[nf][3];
        }
    }
}

extern "C" void kernel_launch(void* const* d_in, const int* in_sizes, int n_in,
                              void* d_out, int out_size) {
    const float *x = nullptr, *w1 = nullptr, *b1 = nullptr, *w2 = nullptr, *b2 = nullptr;
    for (int i = 0; i < n_in; i++) {
        long s = in_sizes[i];
        const float* p = (const float*)d_in[i];
        if      (s == (long)NN*CC*HW)   x  = p;
        else if (s == (long)CC*9*CC*9)  w1 = p;
        else if (s == CC)               b1 = p;
        else if (s == (long)OC2*CC)     w2 = p;
        else if (s == OC2)              b2 = p;
    }
    float* out = (float*)d_out;

    cudaFuncSetAttribute(conv5_mma_kernel,
                         cudaFuncAttributeMaxDynamicSharedMemorySize, CONV5_SMEM);

    fold_kernel<<<(CC*25*CC + 255)/256, 256>>>(w1);
    wprep_kernel<<<(400*4096 + 255)/256, 256>>>();
    xprep_kernel<<<dim3(98, 8, NN), 256>>>(x);
    aggtab_kernel<<<625, 32>>>();
    wagg_kernel<<<dim3(625, 16), 256>>>(w1);
    w2prep_kernel<<<(16*2048 + 255)/256, 256>>>(w2);
    b2eff_kernel<<<1, 128>>>(w2, b1, b2);
    conv5_mma_kernel<<<dim3(56, NN), 256, CONV5_SMEM>>>(out);
    corr_kernel<<<NBAND, 256>>>(out);
}